// round 4
// baseline (speedup 1.0000x reference)
#include <cuda_runtime.h>
#include <cuda_bf16.h>
#include <math.h>
#include <stdint.h>

#define NH   16
#define DHD  64
#define NB   4
#define LQ   1024
#define LK   2048
#define DM   1024
#define MAXPOS 2048

// ---------------- static device scratch (no allocations allowed) ----------------
__device__ float g_Q[(size_t)NB*NH*LQ*DHD];   // [B,H,Lq,64]
__device__ float g_K[(size_t)NB*NH*LK*DHD];   // [B,H,Lk,64]
__device__ float g_V[(size_t)NB*NH*LK*DHD];   // [B,H,Lk,64]

// bf16 split buffers
__device__ __nv_bfloat16 g_Xqh[(size_t)NB*LQ*DM];
__device__ __nv_bfloat16 g_Xql[(size_t)NB*LQ*DM];
__device__ __nv_bfloat16 g_Xkh[(size_t)NB*LK*DM];
__device__ __nv_bfloat16 g_Xkl[(size_t)NB*LK*DM];
__device__ __nv_bfloat16 g_Wh[3][(size_t)DM*DM];
__device__ __nv_bfloat16 g_Wl[3][(size_t)DM*DM];

// ============================ helpers ============================
__device__ __forceinline__ uint32_t smem_u32(const void* p) {
    uint32_t a;
    asm("{ .reg .u64 t; cvta.to.shared.u64 t, %1; cvt.u32.u64 %0, t; }"
        : "=r"(a) : "l"(p));
    return a;
}

__device__ __forceinline__ void cp_async16(uint32_t saddr, const void* gaddr) {
    asm volatile("cp.async.cg.shared.global [%0], [%1], 16;" ::
                 "r"(saddr), "l"(gaddr));
}
__device__ __forceinline__ void cp_commit() {
    asm volatile("cp.async.commit_group;");
}
template <int N>
__device__ __forceinline__ void cp_wait() {
    asm volatile("cp.async.wait_group %0;" :: "n"(N));
}

// mma.sync m16n8k16 bf16 -> f32 (fallback HMMA path, legal in compute_103 PTX)
__device__ __forceinline__ void mma_bf16(float* c, const uint32_t* a, const uint32_t* b) {
    asm volatile(
        "mma.sync.aligned.m16n8k16.row.col.f32.bf16.bf16.f32 "
        "{%0,%1,%2,%3}, {%4,%5,%6,%7}, {%8,%9}, {%0,%1,%2,%3};"
        : "+f"(c[0]), "+f"(c[1]), "+f"(c[2]), "+f"(c[3])
        : "r"(a[0]), "r"(a[1]), "r"(a[2]), "r"(a[3]),
          "r"(b[0]), "r"(b[1]));
}

// =================================================================================
// fp32 -> bf16 (hi, lo) split, vectorized by 4
// =================================================================================
__global__ void split_kernel(const float* __restrict__ x,
                             __nv_bfloat16* __restrict__ hi,
                             __nv_bfloat16* __restrict__ lo, int n4)
{
    int i = blockIdx.x * blockDim.x + threadIdx.x;
    if (i >= n4) return;
    float4 v = ((const float4*)x)[i];
    __nv_bfloat16 h0 = __float2bfloat16(v.x);
    __nv_bfloat16 h1 = __float2bfloat16(v.y);
    __nv_bfloat16 h2 = __float2bfloat16(v.z);
    __nv_bfloat16 h3 = __float2bfloat16(v.w);
    __nv_bfloat16 l0 = __float2bfloat16(v.x - __bfloat162float(h0));
    __nv_bfloat16 l1 = __float2bfloat16(v.y - __bfloat162float(h1));
    __nv_bfloat16 l2 = __float2bfloat16(v.z - __bfloat162float(h2));
    __nv_bfloat16 l3 = __float2bfloat16(v.w - __bfloat162float(h3));
    ((__nv_bfloat162*)hi)[2*i]   = __nv_bfloat162(h0, h1);
    ((__nv_bfloat162*)hi)[2*i+1] = __nv_bfloat162(h2, h3);
    ((__nv_bfloat162*)lo)[2*i]   = __nv_bfloat162(l0, l1);
    ((__nv_bfloat162*)lo)[2*i+1] = __nv_bfloat162(l2, l3);
}

// =================================================================================
// Projection GEMM via mma.sync bf16 split:
//   out[m,n] = sum_k X[m,k]*W[n,k] + bias[n],  D = Ah*Bh + Ah*Bl + Al*Bh
// Block 128x128x32, 8 warps (warp tile 32x64), cp.async double buffer.
// smem row stride 40 bf16 -> conflict-free LDS fragment loads.
// Output scattered to [B,H,L,64].
// =================================================================================
#define BK      32
#define KS_STR  40                         // bf16 units per smem row
#define TILE_BF (128 * KS_STR)             // 5120 bf16 = 10240 B per tile
#define STAGE_BF (4 * TILE_BF)             // Ah, Al, Bh, Bl
#define PROJ_SMEM_BYTES (2 * STAGE_BF * 2) // 81920 B

__global__ __launch_bounds__(256, 1)
void proj_tc(const __nv_bfloat16* __restrict__ Ah_g, const __nv_bfloat16* __restrict__ Al_g,
             const __nv_bfloat16* __restrict__ Bh_g, const __nv_bfloat16* __restrict__ Bl_g,
             const float* __restrict__ bias, float* __restrict__ out, int L)
{
    extern __shared__ __nv_bfloat16 smem[];
    const uint32_t smem_b = smem_u32(smem);

    const int t    = threadIdx.x;
    const int wid  = t >> 5;
    const int lane = t & 31;
    const int g    = lane >> 2;      // group 0..7
    const int t4   = lane & 3;
    const int wm0  = (wid & 3) * 32; // warp row offset in block tile
    const int wn0  = (wid >> 2) * 64;
    const int m0   = blockIdx.x * 128;
    const int n0   = blockIdx.y * 128;

    // global load mapping: 2 uint4 per thread per tile
    const int c0   = t * 2;
    const int row0 = c0 >> 2,       seg0 = c0 & 3;
    const int row1 = (c0 + 1) >> 2, seg1 = (c0 + 1) & 3;

    const int NS = DM / BK;

    auto load_stage = [&](int kc) {
        const int buf = kc & 1;
        const int k0  = kc * BK;
        const uint32_t sb = smem_b + (uint32_t)buf * STAGE_BF * 2;
        const uint32_t so0 = (uint32_t)(row0 * KS_STR + seg0 * 8) * 2;
        const uint32_t so1 = (uint32_t)(row1 * KS_STR + seg1 * 8) * 2;
        const size_t ga0 = (size_t)(m0 + row0) * DM + k0 + seg0 * 8;
        const size_t ga1 = (size_t)(m0 + row1) * DM + k0 + seg1 * 8;
        const size_t gb0 = (size_t)(n0 + row0) * DM + k0 + seg0 * 8;
        const size_t gb1 = (size_t)(n0 + row1) * DM + k0 + seg1 * 8;
        cp_async16(sb + 0 * TILE_BF * 2 + so0, Ah_g + ga0);
        cp_async16(sb + 0 * TILE_BF * 2 + so1, Ah_g + ga1);
        cp_async16(sb + 1 * TILE_BF * 2 + so0, Al_g + ga0);
        cp_async16(sb + 1 * TILE_BF * 2 + so1, Al_g + ga1);
        cp_async16(sb + 2 * TILE_BF * 2 + so0, Bh_g + gb0);
        cp_async16(sb + 2 * TILE_BF * 2 + so1, Bh_g + gb1);
        cp_async16(sb + 3 * TILE_BF * 2 + so0, Bl_g + gb0);
        cp_async16(sb + 3 * TILE_BF * 2 + so1, Bl_g + gb1);
        cp_commit();
    };

    float acc[2][8][4];
#pragma unroll
    for (int i = 0; i < 2; i++)
#pragma unroll
        for (int j = 0; j < 8; j++)
#pragma unroll
            for (int q = 0; q < 4; q++) acc[i][j][q] = 0.0f;

    load_stage(0);

    for (int kc = 0; kc < NS; kc++) {
        if (kc + 1 < NS) { load_stage(kc + 1); cp_wait<1>(); }
        else             { cp_wait<0>(); }
        __syncthreads();

        const __nv_bfloat16* sAh = smem + (size_t)(kc & 1) * STAGE_BF;
        const __nv_bfloat16* sAl = sAh + TILE_BF;
        const __nv_bfloat16* sBh = sAl + TILE_BF;
        const __nv_bfloat16* sBl = sBh + TILE_BF;

#pragma unroll
        for (int ks = 0; ks < BK; ks += 16) {
            uint32_t aH[2][4], aL[2][4], bH[8][2], bL[8][2];
            const int kk = ks + t4 * 2;
#pragma unroll
            for (int i = 0; i < 2; i++) {
                const int r = wm0 + i * 16 + g;
                aH[i][0] = *(const uint32_t*)&sAh[r * KS_STR + kk];
                aH[i][1] = *(const uint32_t*)&sAh[(r + 8) * KS_STR + kk];
                aH[i][2] = *(const uint32_t*)&sAh[r * KS_STR + kk + 8];
                aH[i][3] = *(const uint32_t*)&sAh[(r + 8) * KS_STR + kk + 8];
                aL[i][0] = *(const uint32_t*)&sAl[r * KS_STR + kk];
                aL[i][1] = *(const uint32_t*)&sAl[(r + 8) * KS_STR + kk];
                aL[i][2] = *(const uint32_t*)&sAl[r * KS_STR + kk + 8];
                aL[i][3] = *(const uint32_t*)&sAl[(r + 8) * KS_STR + kk + 8];
            }
#pragma unroll
            for (int j = 0; j < 8; j++) {
                const int n = wn0 + j * 8 + g;
                bH[j][0] = *(const uint32_t*)&sBh[n * KS_STR + kk];
                bH[j][1] = *(const uint32_t*)&sBh[n * KS_STR + kk + 8];
                bL[j][0] = *(const uint32_t*)&sBl[n * KS_STR + kk];
                bL[j][1] = *(const uint32_t*)&sBl[n * KS_STR + kk + 8];
            }
#pragma unroll
            for (int i = 0; i < 2; i++)
#pragma unroll
                for (int j = 0; j < 8; j++) {
                    mma_bf16(acc[i][j], aH[i], bH[j]);
                    mma_bf16(acc[i][j], aH[i], bL[j]);
                    mma_bf16(acc[i][j], aL[i], bH[j]);
                }
        }
        __syncthreads();
    }

    // epilogue: scatter to [B,H,L,64] with bias
#pragma unroll
    for (int i = 0; i < 2; i++) {
#pragma unroll
        for (int j = 0; j < 8; j++) {
            const int cc = n0 + wn0 + j * 8 + t4 * 2;
            const int hh = cc >> 6;
            const int dh = cc & 63;
            const float b0 = __ldg(&bias[cc]);
            const float b1 = __ldg(&bias[cc + 1]);
#pragma unroll
            for (int rr = 0; rr < 2; rr++) {
                const int r = m0 + wm0 + i * 16 + g + rr * 8;
                const int bidx = r / L;
                const int l    = r - bidx * L;
                float2 v;
                v.x = acc[i][j][rr * 2 + 0] + b0;
                v.y = acc[i][j][rr * 2 + 1] + b1;
                *(float2*)(out + ((size_t)(bidx * NH + hh) * L + l) * DHD + dh) = v;
            }
        }
    }
}

// =================================================================================
// Fused attention with relative_key_query position scores (flash-style, fp32).
// (unchanged from R1 — passes with rel_err 1.2e-6)
// =================================================================================
#define SMEM_FLOATS (4*64*65 + 127*65 + 64)
#define SMEM_BYTES  (SMEM_FLOATS * 4)

__global__ __launch_bounds__(256, 2)
void attn_kernel(const float* __restrict__ mask, const float* __restrict__ dist_emb,
                 float* __restrict__ out)
{
    extern __shared__ float sm[];
    float* Qs = sm;
    float* Ks = Qs + 64 * 65;
    float* Vs = Ks + 64 * 65;
    float* Ps = Vs + 64 * 65;
    float* Es = Ps + 64 * 65;
    float* Ms = Es + 127 * 65;

    const int t  = threadIdx.x;
    const int tx = t & 15;
    const int ty = t >> 4;
    const int qt = blockIdx.x;
    const int h  = blockIdx.y;
    const int b  = blockIdx.z;
    const int l0 = qt * 64;

    const float* Qg  = g_Q + ((size_t)(b * NH + h) * LQ + l0) * DHD;
    const float* Kg0 = g_K + (size_t)(b * NH + h) * LK * DHD;
    const float* Vg0 = g_V + (size_t)(b * NH + h) * LK * DHD;

    for (int g = t; g < 64 * 16; g += 256) {
        const int row = g >> 4, c4 = g & 15;
        float4 v = *(const float4*)(Qg + (size_t)row * 64 + c4 * 4);
        float* p = &Qs[row * 65 + c4 * 4];
        p[0] = v.x; p[1] = v.y; p[2] = v.z; p[3] = v.w;
    }

    float O[4][4];
    float mrow[4], lsum[4];
#pragma unroll
    for (int i = 0; i < 4; i++) {
        mrow[i] = -INFINITY; lsum[i] = 0.0f;
#pragma unroll
        for (int j = 0; j < 4; j++) O[i][j] = 0.0f;
    }

    int qb[4], kb[4], eb[7];
#pragma unroll
    for (int i = 0; i < 4; i++) qb[i] = (ty + 16 * i) * 65;
#pragma unroll
    for (int j = 0; j < 4; j++) kb[j] = (tx + 16 * j) * 65;
    const int dl0 = ty - tx + 15;
#pragma unroll
    for (int m = 0; m < 7; m++) eb[m] = (dl0 + 16 * m) * 65;

    for (int kt = 0; kt < LK / 64; kt++) {
        const int r0 = kt * 64;
        __syncthreads();

        for (int g = t; g < 64 * 16; g += 256) {
            const int row = g >> 4, c4 = g & 15;
            float4 kv = *(const float4*)(Kg0 + (size_t)(r0 + row) * 64 + c4 * 4);
            float* pk = &Ks[row * 65 + c4 * 4];
            pk[0] = kv.x; pk[1] = kv.y; pk[2] = kv.z; pk[3] = kv.w;
            float4 vv = *(const float4*)(Vg0 + (size_t)(r0 + row) * 64 + c4 * 4);
            float* pv = &Vs[row * 65 + c4 * 4];
            pv[0] = vv.x; pv[1] = vv.y; pv[2] = vv.z; pv[3] = vv.w;
        }
        const int idx_base = l0 - r0 + (MAXPOS - 64);
        for (int g = t; g < 127 * 16; g += 256) {
            const int row = g >> 4, c4 = g & 15;
            float4 ev = *(const float4*)(dist_emb + (size_t)(idx_base + row) * 64 + c4 * 4);
            float* pe = &Es[row * 65 + c4 * 4];
            pe[0] = ev.x; pe[1] = ev.y; pe[2] = ev.z; pe[3] = ev.w;
        }
        if (t < 64) Ms[t] = mask[(size_t)b * LK + r0 + t];
        __syncthreads();

        float s[4][4];
#pragma unroll
        for (int i = 0; i < 4; i++)
#pragma unroll
            for (int j = 0; j < 4; j++) s[i][j] = 0.0f;

#pragma unroll 4
        for (int d = 0; d < 64; d++) {
            float a[4], kv[4], e[7];
#pragma unroll
            for (int i = 0; i < 4; i++) a[i]  = Qs[qb[i] + d];
#pragma unroll
            for (int j = 0; j < 4; j++) kv[j] = Ks[kb[j] + d];
#pragma unroll
            for (int m = 0; m < 7; m++) e[m]  = Es[eb[m] + d];
#pragma unroll
            for (int i = 0; i < 4; i++)
#pragma unroll
                for (int j = 0; j < 4; j++) {
                    s[i][j] = fmaf(a[i], kv[j], s[i][j]);
                    s[i][j] = fmaf(a[i] + kv[j], e[i - j + 3], s[i][j]);
                }
        }

#pragma unroll
        for (int i = 0; i < 4; i++) {
            float sv[4];
            float rmax = -INFINITY;
#pragma unroll
            for (int j = 0; j < 4; j++) {
                sv[j] = s[i][j] * 0.125f + Ms[tx + 16 * j];
                rmax  = fmaxf(rmax, sv[j]);
            }
#pragma unroll
            for (int off = 1; off < 16; off <<= 1)
                rmax = fmaxf(rmax, __shfl_xor_sync(0xffffffffu, rmax, off));
            const float mnew = fmaxf(mrow[i], rmax);
            const float corr = __expf(mrow[i] - mnew);
            float rs = 0.0f;
#pragma unroll
            for (int j = 0; j < 4; j++) {
                const float p = __expf(sv[j] - mnew);
                s[i][j] = p;
                rs += p;
            }
#pragma unroll
            for (int off = 1; off < 16; off <<= 1)
                rs += __shfl_xor_sync(0xffffffffu, rs, off);
            lsum[i] = lsum[i] * corr + rs;
#pragma unroll
            for (int j = 0; j < 4; j++) O[i][j] *= corr;
            mrow[i] = mnew;
        }

#pragma unroll
        for (int i = 0; i < 4; i++)
#pragma unroll
            for (int j = 0; j < 4; j++)
                Ps[qb[i] + tx + 16 * j] = s[i][j];
        __syncthreads();

#pragma unroll 4
        for (int r = 0; r < 64; r++) {
            float pr[4], vv[4];
#pragma unroll
            for (int i = 0; i < 4; i++) pr[i] = Ps[qb[i] + r];
#pragma unroll
            for (int j = 0; j < 4; j++) vv[j] = Vs[r * 65 + tx + 16 * j];
#pragma unroll
            for (int i = 0; i < 4; i++)
#pragma unroll
                for (int j = 0; j < 4; j++)
                    O[i][j] = fmaf(pr[i], vv[j], O[i][j]);
        }
    }

#pragma unroll
    for (int i = 0; i < 4; i++) {
        const int l = l0 + ty + 16 * i;
        const float inv = 1.0f / lsum[i];
        float* op = out + ((size_t)b * LQ + l) * DM + h * 64;
#pragma unroll
        for (int j = 0; j < 4; j++)
            op[tx + 16 * j] = O[i][j] * inv;
    }
}

// =================================================================================
extern "C" void kernel_launch(void* const* d_in, const int* in_sizes, int n_in,
                              void* d_out, int out_size)
{
    const float* hidden   = (const float*)d_in[0];
    const float* q_hidden = (const float*)d_in[1];
    const float* mask     = (const float*)d_in[2];
    const float* Wq       = (const float*)d_in[3];
    const float* bq       = (const float*)d_in[4];
    const float* Wk       = (const float*)d_in[5];
    const float* bk       = (const float*)d_in[6];
    const float* Wv       = (const float*)d_in[7];
    const float* bv       = (const float*)d_in[8];
    const float* dist     = (const float*)d_in[9];
    float* out = (float*)d_out;

    float *Qp, *Kp, *Vp;
    cudaGetSymbolAddress((void**)&Qp, g_Q);
    cudaGetSymbolAddress((void**)&Kp, g_K);
    cudaGetSymbolAddress((void**)&Vp, g_V);
    __nv_bfloat16 *Xqh, *Xql, *Xkh, *Xkl, *Wh, *Wl;
    cudaGetSymbolAddress((void**)&Xqh, g_Xqh);
    cudaGetSymbolAddress((void**)&Xql, g_Xql);
    cudaGetSymbolAddress((void**)&Xkh, g_Xkh);
    cudaGetSymbolAddress((void**)&Xkl, g_Xkl);
    cudaGetSymbolAddress((void**)&Wh, g_Wh);
    cudaGetSymbolAddress((void**)&Wl, g_Wl);

    cudaFuncSetAttribute(attn_kernel, cudaFuncAttributeMaxDynamicSharedMemorySize,
                         SMEM_BYTES);
    cudaFuncSetAttribute(proj_tc, cudaFuncAttributeMaxDynamicSharedMemorySize,
                         PROJ_SMEM_BYTES);

    // fp32 -> bf16 hi/lo splits
    const int nq  = NB * LQ * DM / 4;
    const int nk  = NB * LK * DM / 4;
    const int nw  = DM * DM / 4;
    split_kernel<<<(nq + 255) / 256, 256>>>(q_hidden, Xqh, Xql, nq);
    split_kernel<<<(nk + 255) / 256, 256>>>(hidden,   Xkh, Xkl, nk);
    split_kernel<<<(nw + 255) / 256, 256>>>(Wq, Wh + 0 * (size_t)DM * DM, Wl + 0 * (size_t)DM * DM, nw);
    split_kernel<<<(nw + 255) / 256, 256>>>(Wk, Wh + 1 * (size_t)DM * DM, Wl + 1 * (size_t)DM * DM, nw);
    split_kernel<<<(nw + 255) / 256, 256>>>(Wv, Wh + 2 * (size_t)DM * DM, Wl + 2 * (size_t)DM * DM, nw);

    // tensor-core projections (mma.sync bf16 split)
    dim3 gq(NB * LQ / 128, DM / 128);   // 32 x 8
    dim3 gk(NB * LK / 128, DM / 128);   // 64 x 8
    proj_tc<<<gq, 256, PROJ_SMEM_BYTES>>>(Xqh, Xql,
        Wh + 0 * (size_t)DM * DM, Wl + 0 * (size_t)DM * DM, bq, Qp, LQ);
    proj_tc<<<gk, 256, PROJ_SMEM_BYTES>>>(Xkh, Xkl,
        Wh + 1 * (size_t)DM * DM, Wl + 1 * (size_t)DM * DM, bk, Kp, LK);
    proj_tc<<<gk, 256, PROJ_SMEM_BYTES>>>(Xkh, Xkl,
        Wh + 2 * (size_t)DM * DM, Wl + 2 * (size_t)DM * DM, bv, Vp, LK);

    // attention
    dim3 ga(LQ / 64, NH, NB);
    attn_kernel<<<ga, 256, SMEM_BYTES>>>(mask, dist, out);
}

// round 5
// speedup vs baseline: 1.6165x; 1.6165x over previous
#include <cuda_runtime.h>
#include <cuda_bf16.h>
#include <math.h>
#include <stdint.h>
#include <string.h>

#define NH   16
#define DHD  64
#define NB   4
#define LQ   1024
#define LK   2048
#define DM   1024
#define MAXPOS 2048
#define STR  72   // bf16 smem row stride

// ---------------- static device scratch ----------------
__device__ float g_Q[(size_t)NB*NH*LQ*DHD];
__device__ float g_K[(size_t)NB*NH*LK*DHD];
__device__ float g_V[(size_t)NB*NH*LK*DHD];

__device__ __nv_bfloat16 g_Xqh[(size_t)NB*LQ*DM];
__device__ __nv_bfloat16 g_Xql[(size_t)NB*LQ*DM];
__device__ __nv_bfloat16 g_Xkh[(size_t)NB*LK*DM];
__device__ __nv_bfloat16 g_Xkl[(size_t)NB*LK*DM];
__device__ __nv_bfloat16 g_Wh[3][(size_t)DM*DM];
__device__ __nv_bfloat16 g_Wl[3][(size_t)DM*DM];

// ============================ helpers ============================
__device__ __forceinline__ uint32_t smem_u32(const void* p) {
    uint32_t a;
    asm("{ .reg .u64 t; cvta.to.shared.u64 t, %1; cvt.u32.u64 %0, t; }"
        : "=r"(a) : "l"(p));
    return a;
}
__device__ __forceinline__ void cp_async16(uint32_t saddr, const void* gaddr) {
    asm volatile("cp.async.cg.shared.global [%0], [%1], 16;" :: "r"(saddr), "l"(gaddr));
}
__device__ __forceinline__ void cp_commit() { asm volatile("cp.async.commit_group;"); }
template <int N>
__device__ __forceinline__ void cp_wait() { asm volatile("cp.async.wait_group %0;" :: "n"(N)); }

__device__ __forceinline__ void mma_bf16(float* c, const uint32_t* a, const uint32_t* b) {
    asm volatile(
        "mma.sync.aligned.m16n8k16.row.col.f32.bf16.bf16.f32 "
        "{%0,%1,%2,%3}, {%4,%5,%6,%7}, {%8,%9}, {%0,%1,%2,%3};"
        : "+f"(c[0]), "+f"(c[1]), "+f"(c[2]), "+f"(c[3])
        : "r"(a[0]), "r"(a[1]), "r"(a[2]), "r"(a[3]), "r"(b[0]), "r"(b[1]));
}
__device__ __forceinline__ uint32_t bfpack(float x, float y) {
    __nv_bfloat162 h(__float2bfloat16(x), __float2bfloat16(y));
    uint32_t u; memcpy(&u, &h, 4); return u;
}
__device__ __forceinline__ void bfsplit(float x, float y, uint32_t& hi, uint32_t& lo) {
    __nv_bfloat16 hx = __float2bfloat16(x), hy = __float2bfloat16(y);
    __nv_bfloat162 h2(hx, hy); memcpy(&hi, &h2, 4);
    __nv_bfloat162 l2(__float2bfloat16(x - __bfloat162float(hx)),
                      __float2bfloat16(y - __bfloat162float(hy)));
    memcpy(&lo, &l2, 4);
}

// =================================================================================
__global__ void split_kernel(const float* __restrict__ x,
                             __nv_bfloat16* __restrict__ hi,
                             __nv_bfloat16* __restrict__ lo, int n4)
{
    int i = blockIdx.x * blockDim.x + threadIdx.x;
    if (i >= n4) return;
    float4 v = ((const float4*)x)[i];
    uint32_t h0, l0, h1, l1;
    bfsplit(v.x, v.y, h0, l0);
    bfsplit(v.z, v.w, h1, l1);
    ((uint32_t*)hi)[2*i] = h0; ((uint32_t*)hi)[2*i+1] = h1;
    ((uint32_t*)lo)[2*i] = l0; ((uint32_t*)lo)[2*i+1] = l1;
}

// =================================================================================
// Projection GEMM (unchanged from R3, proven): out scattered to [B,H,L,64] fp32
// =================================================================================
#define BK      32
#define KS_STR  40
#define TILE_BF (128 * KS_STR)
#define STAGE_BF (4 * TILE_BF)
#define PROJ_SMEM_BYTES (2 * STAGE_BF * 2)

__global__ __launch_bounds__(256, 1)
void proj_tc(const __nv_bfloat16* __restrict__ Ah_g, const __nv_bfloat16* __restrict__ Al_g,
             const __nv_bfloat16* __restrict__ Bh_g, const __nv_bfloat16* __restrict__ Bl_g,
             const float* __restrict__ bias, float* __restrict__ out, int L)
{
    extern __shared__ __nv_bfloat16 smem[];
    const uint32_t smem_b = smem_u32(smem);
    const int t = threadIdx.x, lane = t & 31;
    const int wid = t >> 5, g = lane >> 2, t4 = lane & 3;
    const int wm0 = (wid & 3) * 32, wn0 = (wid >> 2) * 64;
    const int m0 = blockIdx.x * 128, n0 = blockIdx.y * 128;
    const int c0 = t * 2;
    const int row0 = c0 >> 2, seg0 = c0 & 3;
    const int row1 = (c0 + 1) >> 2, seg1 = (c0 + 1) & 3;
    const int NS = DM / BK;

    auto load_stage = [&](int kc) {
        const int k0 = kc * BK;
        const uint32_t sb = smem_b + (uint32_t)(kc & 1) * STAGE_BF * 2;
        const uint32_t so0 = (uint32_t)(row0 * KS_STR + seg0 * 8) * 2;
        const uint32_t so1 = (uint32_t)(row1 * KS_STR + seg1 * 8) * 2;
        const size_t ga0 = (size_t)(m0 + row0) * DM + k0 + seg0 * 8;
        const size_t ga1 = (size_t)(m0 + row1) * DM + k0 + seg1 * 8;
        const size_t gb0 = (size_t)(n0 + row0) * DM + k0 + seg0 * 8;
        const size_t gb1 = (size_t)(n0 + row1) * DM + k0 + seg1 * 8;
        cp_async16(sb + 0 * TILE_BF * 2 + so0, Ah_g + ga0);
        cp_async16(sb + 0 * TILE_BF * 2 + so1, Ah_g + ga1);
        cp_async16(sb + 1 * TILE_BF * 2 + so0, Al_g + ga0);
        cp_async16(sb + 1 * TILE_BF * 2 + so1, Al_g + ga1);
        cp_async16(sb + 2 * TILE_BF * 2 + so0, Bh_g + gb0);
        cp_async16(sb + 2 * TILE_BF * 2 + so1, Bh_g + gb1);
        cp_async16(sb + 3 * TILE_BF * 2 + so0, Bl_g + gb0);
        cp_async16(sb + 3 * TILE_BF * 2 + so1, Bl_g + gb1);
        cp_commit();
    };

    float acc[2][8][4];
#pragma unroll
    for (int i = 0; i < 2; i++)
#pragma unroll
        for (int j = 0; j < 8; j++)
#pragma unroll
            for (int q = 0; q < 4; q++) acc[i][j][q] = 0.0f;

    load_stage(0);
    for (int kc = 0; kc < NS; kc++) {
        if (kc + 1 < NS) { load_stage(kc + 1); cp_wait<1>(); }
        else             { cp_wait<0>(); }
        __syncthreads();
        const __nv_bfloat16* sAh = smem + (size_t)(kc & 1) * STAGE_BF;
        const __nv_bfloat16* sAl = sAh + TILE_BF;
        const __nv_bfloat16* sBh = sAl + TILE_BF;
        const __nv_bfloat16* sBl = sBh + TILE_BF;
#pragma unroll
        for (int ks = 0; ks < BK; ks += 16) {
            uint32_t aH[2][4], aL[2][4], bH[8][2], bL[8][2];
            const int kk = ks + t4 * 2;
#pragma unroll
            for (int i = 0; i < 2; i++) {
                const int r = wm0 + i * 16 + g;
                aH[i][0] = *(const uint32_t*)&sAh[r * KS_STR + kk];
                aH[i][1] = *(const uint32_t*)&sAh[(r + 8) * KS_STR + kk];
                aH[i][2] = *(const uint32_t*)&sAh[r * KS_STR + kk + 8];
                aH[i][3] = *(const uint32_t*)&sAh[(r + 8) * KS_STR + kk + 8];
                aL[i][0] = *(const uint32_t*)&sAl[r * KS_STR + kk];
                aL[i][1] = *(const uint32_t*)&sAl[(r + 8) * KS_STR + kk];
                aL[i][2] = *(const uint32_t*)&sAl[r * KS_STR + kk + 8];
                aL[i][3] = *(const uint32_t*)&sAl[(r + 8) * KS_STR + kk + 8];
            }
#pragma unroll
            for (int j = 0; j < 8; j++) {
                const int n = wn0 + j * 8 + g;
                bH[j][0] = *(const uint32_t*)&sBh[n * KS_STR + kk];
                bH[j][1] = *(const uint32_t*)&sBh[n * KS_STR + kk + 8];
                bL[j][0] = *(const uint32_t*)&sBl[n * KS_STR + kk];
                bL[j][1] = *(const uint32_t*)&sBl[n * KS_STR + kk + 8];
            }
#pragma unroll
            for (int i = 0; i < 2; i++)
#pragma unroll
                for (int j = 0; j < 8; j++) {
                    mma_bf16(acc[i][j], aH[i], bH[j]);
                    mma_bf16(acc[i][j], aH[i], bL[j]);
                    mma_bf16(acc[i][j], aL[i], bH[j]);
                }
        }
        __syncthreads();
    }
#pragma unroll
    for (int i = 0; i < 2; i++)
#pragma unroll
        for (int j = 0; j < 8; j++) {
            const int cc = n0 + wn0 + j * 8 + t4 * 2;
            const int hh = cc >> 6, dh = cc & 63;
            const float b0 = __ldg(&bias[cc]), b1 = __ldg(&bias[cc + 1]);
#pragma unroll
            for (int rr = 0; rr < 2; rr++) {
                const int r = m0 + wm0 + i * 16 + g + rr * 8;
                const int bidx = r / L, l = r - bidx * L;
                float2 v;
                v.x = acc[i][j][rr * 2 + 0] + b0;
                v.y = acc[i][j][rr * 2 + 1] + b1;
                *(float2*)(out + ((size_t)(bidx * NH + hh) * L + l) * DHD + dh) = v;
            }
        }
}

// =================================================================================
// Tensor-core attention with relative_key_query positions.
// =================================================================================
#define SM_S23 0
#define SM_SL  67584
#define SM_QH  84992
#define SM_QL  94208
#define SM_KH  103424
#define SM_KL  112640
#define SM_VTH 121856
#define SM_VTL 131072
#define SM_PH  140288
#define SM_PL  149504
#define SM_ES  158720
#define SM_MS  177152
#define SM_MR  177408
#define SM_LS  177664
#define SM_CS  177920
#define ATTN_SMEM 178176

__global__ __launch_bounds__(256, 1)
void attn_tc(const float* __restrict__ mask, const float* __restrict__ dist,
             float* __restrict__ out)
{
    extern __shared__ char smc[];
    float* S23 = (float*)(smc + SM_S23);   // [128][132]
    float* Sl  = (float*)(smc + SM_SL);    // [64][68]
    __nv_bfloat16* Qh  = (__nv_bfloat16*)(smc + SM_QH);
    __nv_bfloat16* Ql  = (__nv_bfloat16*)(smc + SM_QL);
    __nv_bfloat16* Kh  = (__nv_bfloat16*)(smc + SM_KH);
    __nv_bfloat16* Kl  = (__nv_bfloat16*)(smc + SM_KL);
    __nv_bfloat16* Vth = (__nv_bfloat16*)(smc + SM_VTH); // [d][r] swizzled
    __nv_bfloat16* Vtl = (__nv_bfloat16*)(smc + SM_VTL);
    __nv_bfloat16* Ph  = (__nv_bfloat16*)(smc + SM_PH);
    __nv_bfloat16* Pl  = (__nv_bfloat16*)(smc + SM_PL);
    __nv_bfloat16* Es  = (__nv_bfloat16*)(smc + SM_ES);  // [128][STR]
    float* Ms = (float*)(smc + SM_MS);
    float* Mr = (float*)(smc + SM_MR);
    float* Ls = (float*)(smc + SM_LS);
    float* Cs = (float*)(smc + SM_CS);

    const int t = threadIdx.x, lane = t & 31, w = t >> 5;
    const int g = lane >> 2, t4 = lane & 3;
    const int sm0 = (w & 1) * 32, sn0 = (w >> 1) * 16; // QK/PV grid 2m x 4n
    const int en0 = (w >> 2) * 64;                      // E grid 4m x 2n
    const int emg = (w & 3) * 32;
    const int l0 = blockIdx.x * 64, hd = blockIdx.y, b = blockIdx.z;

    const float* Qg = g_Q + ((size_t)(b * NH + hd) * LQ + l0) * DHD;
    const float* Kg = g_K + (size_t)(b * NH + hd) * LK * DHD;
    const float* Vg = g_V + (size_t)(b * NH + hd) * LK * DHD;

#pragma unroll
    for (int i = 0; i < 8; i++) {
        int q = t + 256 * i, row = q >> 5, c2 = q & 31;
        float2 v = *(const float2*)(Qg + row * 64 + 2 * c2);
        uint32_t hi, lo; bfsplit(v.x, v.y, hi, lo);
        *(uint32_t*)&Qh[row * STR + 2 * c2] = hi;
        *(uint32_t*)&Ql[row * STR + 2 * c2] = lo;
    }
    if (t < 64) { Mr[t] = -1e30f; Ls[t] = 0.f; }
    if (t < 36) ((uint32_t*)&Es[127 * STR])[t] = 0u;

    float O[2][2][4];
#pragma unroll
    for (int i = 0; i < 2; i++)
#pragma unroll
        for (int j = 0; j < 2; j++)
#pragma unroll
            for (int q = 0; q < 4; q++) O[i][j][q] = 0.f;

    for (int kt = 0; kt < LK / 64; kt++) {
        const int r0 = kt * 64;
        __syncthreads();

        // ---- K load+split ----
#pragma unroll
        for (int i = 0; i < 8; i++) {
            int q = t + 256 * i, row = q >> 5, c2 = q & 31;
            float2 v = *(const float2*)(Kg + (size_t)(r0 + row) * 64 + 2 * c2);
            uint32_t hi, lo; bfsplit(v.x, v.y, hi, lo);
            *(uint32_t*)&Kh[row * STR + 2 * c2] = hi;
            *(uint32_t*)&Kl[row * STR + 2 * c2] = lo;
        }
        // ---- V transpose+split (swizzled) ----
#pragma unroll
        for (int i = 0; i < 4; i++) {
            int qx = t + 256 * i, d2 = qx & 31, r2 = qx >> 5;
            float2 v0 = *(const float2*)(Vg + (size_t)(r0 + 2 * r2) * 64 + 2 * d2);
            float2 v1 = *(const float2*)(Vg + (size_t)(r0 + 2 * r2 + 1) * 64 + 2 * d2);
            int sw = (d2 >> 2) & 3, rr = 2 * (r2 ^ sw);
            uint32_t hi, lo;
            bfsplit(v0.x, v1.x, hi, lo);
            *(uint32_t*)&Vth[(2 * d2) * STR + rr] = hi;
            *(uint32_t*)&Vtl[(2 * d2) * STR + rr] = lo;
            bfsplit(v0.y, v1.y, hi, lo);
            *(uint32_t*)&Vth[(2 * d2 + 1) * STR + rr] = hi;
            *(uint32_t*)&Vtl[(2 * d2 + 1) * STR + rr] = lo;
        }
        // ---- E window (bf16 hi only) ----
        const int ebase = l0 - r0 + (MAXPOS - 64);
#pragma unroll
        for (int i = 0; i < 16; i++) {
            int qx = t + 256 * i;
            if (qx < 127 * 32) {
                int row = qx >> 5, c2 = qx & 31;
                float2 v = *(const float2*)(dist + (size_t)(ebase + row) * 64 + 2 * c2);
                *(uint32_t*)&Es[row * STR + 2 * c2] = bfpack(v.x, v.y);
            }
        }
        if (t < 64) Ms[t] = mask[(size_t)b * LK + r0 + t];
        __syncthreads();

        // ---- GEMM1: S23 = [Qh;Kh] @ Es^T ----
        {
            const __nv_bfloat16* Ab = ((w & 3) < 2) ? Qh : Kh;
            const int am = (w & 1) * 32;
            float ea[2][8][4];
#pragma unroll
            for (int i = 0; i < 2; i++)
#pragma unroll
                for (int j = 0; j < 8; j++)
#pragma unroll
                    for (int q = 0; q < 4; q++) ea[i][j][q] = 0.f;
#pragma unroll
            for (int k4 = 0; k4 < 4; k4++) {
                const int kk = k4 * 16 + t4 * 2;
                uint32_t af[2][4];
#pragma unroll
                for (int i = 0; i < 2; i++) {
                    const int r = am + i * 16 + g;
                    af[i][0] = *(const uint32_t*)&Ab[r * STR + kk];
                    af[i][1] = *(const uint32_t*)&Ab[(r + 8) * STR + kk];
                    af[i][2] = *(const uint32_t*)&Ab[r * STR + kk + 8];
                    af[i][3] = *(const uint32_t*)&Ab[(r + 8) * STR + kk + 8];
                }
#pragma unroll
                for (int j = 0; j < 8; j++) {
                    const int n = en0 + j * 8 + g;
                    uint32_t bf2[2];
                    bf2[0] = *(const uint32_t*)&Es[n * STR + kk];
                    bf2[1] = *(const uint32_t*)&Es[n * STR + kk + 8];
                    mma_bf16(ea[0][j], af[0], bf2);
                    mma_bf16(ea[1][j], af[1], bf2);
                }
            }
#pragma unroll
            for (int i = 0; i < 2; i++)
#pragma unroll
                for (int j = 0; j < 8; j++) {
                    const int m = emg + i * 16 + g, n = en0 + j * 8 + t4 * 2;
                    *(float2*)&S23[m * 132 + n] = make_float2(ea[i][j][0], ea[i][j][1]);
                    *(float2*)&S23[(m + 8) * 132 + n] = make_float2(ea[i][j][2], ea[i][j][3]);
                }
        }
        // ---- GEMM2: Q@K^T split ----
        float sc[2][2][4];
#pragma unroll
        for (int i = 0; i < 2; i++)
#pragma unroll
            for (int j = 0; j < 2; j++)
#pragma unroll
                for (int q = 0; q < 4; q++) sc[i][j][q] = 0.f;
#pragma unroll
        for (int k4 = 0; k4 < 4; k4++) {
            const int kk = k4 * 16 + t4 * 2;
            uint32_t aH[2][4], aL[2][4];
#pragma unroll
            for (int i = 0; i < 2; i++) {
                const int r = sm0 + i * 16 + g;
                aH[i][0] = *(const uint32_t*)&Qh[r * STR + kk];
                aH[i][1] = *(const uint32_t*)&Qh[(r + 8) * STR + kk];
                aH[i][2] = *(const uint32_t*)&Qh[r * STR + kk + 8];
                aH[i][3] = *(const uint32_t*)&Qh[(r + 8) * STR + kk + 8];
                aL[i][0] = *(const uint32_t*)&Ql[r * STR + kk];
                aL[i][1] = *(const uint32_t*)&Ql[(r + 8) * STR + kk];
                aL[i][2] = *(const uint32_t*)&Ql[r * STR + kk + 8];
                aL[i][3] = *(const uint32_t*)&Ql[(r + 8) * STR + kk + 8];
            }
#pragma unroll
            for (int j = 0; j < 2; j++) {
                const int n = sn0 + j * 8 + g;
                uint32_t bH2[2], bL2[2];
                bH2[0] = *(const uint32_t*)&Kh[n * STR + kk];
                bH2[1] = *(const uint32_t*)&Kh[n * STR + kk + 8];
                bL2[0] = *(const uint32_t*)&Kl[n * STR + kk];
                bL2[1] = *(const uint32_t*)&Kl[n * STR + kk + 8];
#pragma unroll
                for (int i = 0; i < 2; i++) {
                    mma_bf16(sc[i][j], aH[i], bH2);
                    mma_bf16(sc[i][j], aH[i], bL2);
                    mma_bf16(sc[i][j], aL[i], bH2);
                }
            }
        }
        __syncthreads();

        // ---- logits: gather S23 diagonals + mask ----
#pragma unroll
        for (int i = 0; i < 2; i++)
#pragma unroll
            for (int j = 0; j < 2; j++) {
                const int ri = sn0 + j * 8 + t4 * 2;
#pragma unroll
                for (int ch = 0; ch < 2; ch++) {
                    const int li = sm0 + i * 16 + g + ch * 8;
                    const int nn = li - ri + 63;
                    float t0 = S23[li * 132 + nn] + S23[(64 + ri) * 132 + nn];
                    float t1 = S23[li * 132 + nn - 1] + S23[(65 + ri) * 132 + nn - 1];
                    float2 lv;
                    lv.x = (sc[i][j][ch * 2 + 0] + t0) * 0.125f + Ms[ri];
                    lv.y = (sc[i][j][ch * 2 + 1] + t1) * 0.125f + Ms[ri + 1];
                    *(float2*)&Sl[li * 68 + ri] = lv;
                }
            }
        __syncthreads();

        // ---- online softmax (4 threads per row) ----
        {
            const int row = t >> 2, qq = t & 3;
            float v[16], mx = -1e30f;
#pragma unroll
            for (int c = 0; c < 16; c++) {
                v[c] = Sl[row * 68 + qq * 16 + c];
                mx = fmaxf(mx, v[c]);
            }
            mx = fmaxf(mx, __shfl_xor_sync(0xffffffffu, mx, 1));
            mx = fmaxf(mx, __shfl_xor_sync(0xffffffffu, mx, 2));
            const float mold = Mr[row];
            const float mnew = fmaxf(mold, mx);
            const float corr = __expf(mold - mnew);
            float s = 0.f;
#pragma unroll
            for (int c = 0; c < 16; c++) { v[c] = __expf(v[c] - mnew); s += v[c]; }
            s += __shfl_xor_sync(0xffffffffu, s, 1);
            s += __shfl_xor_sync(0xffffffffu, s, 2);
            if (qq == 0) { Ls[row] = Ls[row] * corr + s; Mr[row] = mnew; Cs[row] = corr; }
#pragma unroll
            for (int c = 0; c < 16; c += 2) {
                uint32_t hi, lo; bfsplit(v[c], v[c + 1], hi, lo);
                *(uint32_t*)&Ph[row * STR + qq * 16 + c] = hi;
                *(uint32_t*)&Pl[row * STR + qq * 16 + c] = lo;
            }
        }
        __syncthreads();

        // ---- PV: O = O*corr + P@V ----
#pragma unroll
        for (int i = 0; i < 2; i++) {
            const float c0 = Cs[sm0 + i * 16 + g];
            const float c1 = Cs[sm0 + i * 16 + g + 8];
#pragma unroll
            for (int j = 0; j < 2; j++) {
                O[i][j][0] *= c0; O[i][j][1] *= c0;
                O[i][j][2] *= c1; O[i][j][3] *= c1;
            }
        }
#pragma unroll
        for (int k4 = 0; k4 < 4; k4++) {
            const int kk = k4 * 16 + t4 * 2;
            uint32_t aH[2][4], aL[2][4];
#pragma unroll
            for (int i = 0; i < 2; i++) {
                const int r = sm0 + i * 16 + g;
                aH[i][0] = *(const uint32_t*)&Ph[r * STR + kk];
                aH[i][1] = *(const uint32_t*)&Ph[(r + 8) * STR + kk];
                aH[i][2] = *(const uint32_t*)&Ph[r * STR + kk + 8];
                aH[i][3] = *(const uint32_t*)&Ph[(r + 8) * STR + kk + 8];
                aL[i][0] = *(const uint32_t*)&Pl[r * STR + kk];
                aL[i][1] = *(const uint32_t*)&Pl[(r + 8) * STR + kk];
                aL[i][2] = *(const uint32_t*)&Pl[r * STR + kk + 8];
                aL[i][3] = *(const uint32_t*)&Pl[(r + 8) * STR + kk + 8];
            }
#pragma unroll
            for (int j = 0; j < 2; j++) {
                const int d = sn0 + j * 8 + g;
                const int sw = (d >> 3) & 3;
                const int p0 = d * STR + 2 * ((kk >> 1) ^ sw);
                const int p1 = d * STR + 2 * (((kk + 8) >> 1) ^ sw);
                uint32_t bH2[2], bL2[2];
                bH2[0] = *(const uint32_t*)&Vth[p0];
                bH2[1] = *(const uint32_t*)&Vth[p1];
                bL2[0] = *(const uint32_t*)&Vtl[p0];
                bL2[1] = *(const uint32_t*)&Vtl[p1];
#pragma unroll
                for (int i = 0; i < 2; i++) {
                    mma_bf16(O[i][j], aH[i], bH2);
                    mma_bf16(O[i][j], aH[i], bL2);
                    mma_bf16(O[i][j], aL[i], bH2);
                }
            }
        }
    }

    // ---- output [B, Lq, H*64] ----
#pragma unroll
    for (int i = 0; i < 2; i++)
#pragma unroll
        for (int ch = 0; ch < 2; ch++) {
            const int li = sm0 + i * 16 + g + ch * 8;
            const float inv = 1.0f / Ls[li];
#pragma unroll
            for (int j = 0; j < 2; j++) {
                const int d = sn0 + j * 8 + t4 * 2;
                float2 o;
                o.x = O[i][j][ch * 2 + 0] * inv;
                o.y = O[i][j][ch * 2 + 1] * inv;
                *(float2*)(out + ((size_t)(b * LQ) + l0 + li) * DM + hd * 64 + d) = o;
            }
        }
}

// =================================================================================
extern "C" void kernel_launch(void* const* d_in, const int* in_sizes, int n_in,
                              void* d_out, int out_size)
{
    const float* hidden   = (const float*)d_in[0];
    const float* q_hidden = (const float*)d_in[1];
    const float* mask     = (const float*)d_in[2];
    const float* Wq       = (const float*)d_in[3];
    const float* bq       = (const float*)d_in[4];
    const float* Wk       = (const float*)d_in[5];
    const float* bk       = (const float*)d_in[6];
    const float* Wv       = (const float*)d_in[7];
    const float* bv       = (const float*)d_in[8];
    const float* dist     = (const float*)d_in[9];
    float* out = (float*)d_out;

    float *Qp, *Kp, *Vp;
    cudaGetSymbolAddress((void**)&Qp, g_Q);
    cudaGetSymbolAddress((void**)&Kp, g_K);
    cudaGetSymbolAddress((void**)&Vp, g_V);
    __nv_bfloat16 *Xqh, *Xql, *Xkh, *Xkl, *Wh, *Wl;
    cudaGetSymbolAddress((void**)&Xqh, g_Xqh);
    cudaGetSymbolAddress((void**)&Xql, g_Xql);
    cudaGetSymbolAddress((void**)&Xkh, g_Xkh);
    cudaGetSymbolAddress((void**)&Xkl, g_Xkl);
    cudaGetSymbolAddress((void**)&Wh, g_Wh);
    cudaGetSymbolAddress((void**)&Wl, g_Wl);

    cudaFuncSetAttribute(proj_tc, cudaFuncAttributeMaxDynamicSharedMemorySize,
                         PROJ_SMEM_BYTES);
    cudaFuncSetAttribute(attn_tc, cudaFuncAttributeMaxDynamicSharedMemorySize,
                         ATTN_SMEM);

    const int nq = NB * LQ * DM / 4;
    const int nk = NB * LK * DM / 4;
    const int nw = DM * DM / 4;
    split_kernel<<<(nq + 255) / 256, 256>>>(q_hidden, Xqh, Xql, nq);
    split_kernel<<<(nk + 255) / 256, 256>>>(hidden,   Xkh, Xkl, nk);
    split_kernel<<<(nw + 255) / 256, 256>>>(Wq, Wh + 0 * (size_t)DM * DM, Wl + 0 * (size_t)DM * DM, nw);
    split_kernel<<<(nw + 255) / 256, 256>>>(Wk, Wh + 1 * (size_t)DM * DM, Wl + 1 * (size_t)DM * DM, nw);
    split_kernel<<<(nw + 255) / 256, 256>>>(Wv, Wh + 2 * (size_t)DM * DM, Wl + 2 * (size_t)DM * DM, nw);

    dim3 gq(NB * LQ / 128, DM / 128);
    dim3 gk(NB * LK / 128, DM / 128);
    proj_tc<<<gq, 256, PROJ_SMEM_BYTES>>>(Xqh, Xql,
        Wh + 0 * (size_t)DM * DM, Wl + 0 * (size_t)DM * DM, bq, Qp, LQ);
    proj_tc<<<gk, 256, PROJ_SMEM_BYTES>>>(Xkh, Xkl,
        Wh + 1 * (size_t)DM * DM, Wl + 1 * (size_t)DM * DM, bk, Kp, LK);
    proj_tc<<<gk, 256, PROJ_SMEM_BYTES>>>(Xkh, Xkl,
        Wh + 2 * (size_t)DM * DM, Wl + 2 * (size_t)DM * DM, bv, Vp, LK);

    dim3 ga(LQ / 64, NH, NB);
    attn_tc<<<ga, 256, ATTN_SMEM>>>(mask, dist, out);
}

// round 6
// speedup vs baseline: 1.8903x; 1.1693x over previous
#include <cuda_runtime.h>
#include <cuda_bf16.h>
#include <math.h>
#include <stdint.h>
#include <string.h>

#define NH   16
#define DHD  64
#define NB   4
#define LQ   1024
#define LK   2048
#define DM   1024
#define MAXPOS 2048
#define STR  72    // bf16 smem row stride (144B)
#define SSTR 136   // S23 bf16 stride

// ---------------- static device scratch ----------------
__device__ __nv_bfloat16 g_Qh[(size_t)NB*NH*LQ*DHD];
__device__ __nv_bfloat16 g_Ql[(size_t)NB*NH*LQ*DHD];
__device__ __nv_bfloat16 g_Kh[(size_t)NB*NH*LK*DHD];
__device__ __nv_bfloat16 g_Kl[(size_t)NB*NH*LK*DHD];
__device__ __nv_bfloat16 g_VtH[(size_t)NB*NH*DHD*LK];  // [b,h][d][r]
__device__ __nv_bfloat16 g_VtL[(size_t)NB*NH*DHD*LK];
__device__ __nv_bfloat16 g_EbH[(size_t)(2*MAXPOS-1)*DHD];

__device__ __nv_bfloat16 g_Xqh[(size_t)NB*LQ*DM];
__device__ __nv_bfloat16 g_Xql[(size_t)NB*LQ*DM];
__device__ __nv_bfloat16 g_Xkh[(size_t)NB*LK*DM];
__device__ __nv_bfloat16 g_Xkl[(size_t)NB*LK*DM];
__device__ __nv_bfloat16 g_Wh[3][(size_t)DM*DM];
__device__ __nv_bfloat16 g_Wl[3][(size_t)DM*DM];

// ============================ helpers ============================
__device__ __forceinline__ uint32_t smem_u32(const void* p) {
    uint32_t a;
    asm("{ .reg .u64 t; cvta.to.shared.u64 t, %1; cvt.u32.u64 %0, t; }"
        : "=r"(a) : "l"(p));
    return a;
}
__device__ __forceinline__ void cp_async16(uint32_t saddr, const void* gaddr) {
    asm volatile("cp.async.cg.shared.global [%0], [%1], 16;" :: "r"(saddr), "l"(gaddr));
}
__device__ __forceinline__ void cp_commit() { asm volatile("cp.async.commit_group;"); }
template <int N>
__device__ __forceinline__ void cp_wait() { asm volatile("cp.async.wait_group %0;" :: "n"(N)); }

__device__ __forceinline__ void mma_bf16(float* c, const uint32_t* a, const uint32_t* b) {
    asm volatile(
        "mma.sync.aligned.m16n8k16.row.col.f32.bf16.bf16.f32 "
        "{%0,%1,%2,%3}, {%4,%5,%6,%7}, {%8,%9}, {%0,%1,%2,%3};"
        : "+f"(c[0]), "+f"(c[1]), "+f"(c[2]), "+f"(c[3])
        : "r"(a[0]), "r"(a[1]), "r"(a[2]), "r"(a[3]), "r"(b[0]), "r"(b[1]));
}
__device__ __forceinline__ uint32_t bfpack(float x, float y) {
    __nv_bfloat162 h(__float2bfloat16(x), __float2bfloat16(y));
    uint32_t u; memcpy(&u, &h, 4); return u;
}
__device__ __forceinline__ void bfsplit(float x, float y, uint32_t& hi, uint32_t& lo) {
    __nv_bfloat16 hx = __float2bfloat16(x), hy = __float2bfloat16(y);
    __nv_bfloat162 h2(hx, hy); memcpy(&hi, &h2, 4);
    __nv_bfloat162 l2(__float2bfloat16(x - __bfloat162float(hx)),
                      __float2bfloat16(y - __bfloat162float(hy)));
    memcpy(&lo, &l2, 4);
}

// =================================================================================
__global__ void split_kernel(const float* __restrict__ x,
                             __nv_bfloat16* __restrict__ hi,
                             __nv_bfloat16* __restrict__ lo, int n4)
{
    int i = blockIdx.x * blockDim.x + threadIdx.x;
    if (i >= n4) return;
    float4 v = ((const float4*)x)[i];
    uint32_t h0, l0, h1, l1;
    bfsplit(v.x, v.y, h0, l0);
    bfsplit(v.z, v.w, h1, l1);
    ((uint32_t*)hi)[2*i] = h0; ((uint32_t*)hi)[2*i+1] = h1;
    ((uint32_t*)lo)[2*i] = l0; ((uint32_t*)lo)[2*i+1] = l1;
}
__global__ void conv_kernel(const float* __restrict__ x,
                            __nv_bfloat16* __restrict__ y, int n4)
{
    int i = blockIdx.x * blockDim.x + threadIdx.x;
    if (i >= n4) return;
    float4 v = ((const float4*)x)[i];
    ((uint32_t*)y)[2*i]   = bfpack(v.x, v.y);
    ((uint32_t*)y)[2*i+1] = bfpack(v.z, v.w);
}

// =================================================================================
// Projection GEMM; epilogue emits bf16 hi/lo.  mode 0: [B,H,L,64]; mode 1: V^T [B,H,64,LK]
// =================================================================================
#define BK      32
#define KS_STR  40
#define TILE_BF (128 * KS_STR)
#define STAGE_BF (4 * TILE_BF)
#define PROJ_SMEM_BYTES (2 * STAGE_BF * 2)

__global__ __launch_bounds__(256, 1)
void proj_tc(const __nv_bfloat16* __restrict__ Ah_g, const __nv_bfloat16* __restrict__ Al_g,
             const __nv_bfloat16* __restrict__ Bh_g, const __nv_bfloat16* __restrict__ Bl_g,
             const float* __restrict__ bias,
             __nv_bfloat16* __restrict__ outH, __nv_bfloat16* __restrict__ outL,
             int L, int mode)
{
    extern __shared__ __nv_bfloat16 smem[];
    const uint32_t smem_b = smem_u32(smem);
    const int t = threadIdx.x, lane = t & 31;
    const int wid = t >> 5, g = lane >> 2, t4 = lane & 3;
    const int wm0 = (wid & 3) * 32, wn0 = (wid >> 2) * 64;
    const int m0 = blockIdx.x * 128, n0 = blockIdx.y * 128;
    const int c0 = t * 2;
    const int row0 = c0 >> 2, seg0 = c0 & 3;
    const int row1 = (c0 + 1) >> 2, seg1 = (c0 + 1) & 3;
    const int NS = DM / BK;

    auto load_stage = [&](int kc) {
        const int k0 = kc * BK;
        const uint32_t sb = smem_b + (uint32_t)(kc & 1) * STAGE_BF * 2;
        const uint32_t so0 = (uint32_t)(row0 * KS_STR + seg0 * 8) * 2;
        const uint32_t so1 = (uint32_t)(row1 * KS_STR + seg1 * 8) * 2;
        const size_t ga0 = (size_t)(m0 + row0) * DM + k0 + seg0 * 8;
        const size_t ga1 = (size_t)(m0 + row1) * DM + k0 + seg1 * 8;
        const size_t gb0 = (size_t)(n0 + row0) * DM + k0 + seg0 * 8;
        const size_t gb1 = (size_t)(n0 + row1) * DM + k0 + seg1 * 8;
        cp_async16(sb + 0 * TILE_BF * 2 + so0, Ah_g + ga0);
        cp_async16(sb + 0 * TILE_BF * 2 + so1, Ah_g + ga1);
        cp_async16(sb + 1 * TILE_BF * 2 + so0, Al_g + ga0);
        cp_async16(sb + 1 * TILE_BF * 2 + so1, Al_g + ga1);
        cp_async16(sb + 2 * TILE_BF * 2 + so0, Bh_g + gb0);
        cp_async16(sb + 2 * TILE_BF * 2 + so1, Bh_g + gb1);
        cp_async16(sb + 3 * TILE_BF * 2 + so0, Bl_g + gb0);
        cp_async16(sb + 3 * TILE_BF * 2 + so1, Bl_g + gb1);
        cp_commit();
    };

    float acc[2][8][4];
#pragma unroll
    for (int i = 0; i < 2; i++)
#pragma unroll
        for (int j = 0; j < 8; j++)
#pragma unroll
            for (int q = 0; q < 4; q++) acc[i][j][q] = 0.0f;

    load_stage(0);
    for (int kc = 0; kc < NS; kc++) {
        if (kc + 1 < NS) { load_stage(kc + 1); cp_wait<1>(); }
        else             { cp_wait<0>(); }
        __syncthreads();
        const __nv_bfloat16* sAh = smem + (size_t)(kc & 1) * STAGE_BF;
        const __nv_bfloat16* sAl = sAh + TILE_BF;
        const __nv_bfloat16* sBh = sAl + TILE_BF;
        const __nv_bfloat16* sBl = sBh + TILE_BF;
#pragma unroll
        for (int ks = 0; ks < BK; ks += 16) {
            uint32_t aH[2][4], aL[2][4], bH[8][2], bL[8][2];
            const int kk = ks + t4 * 2;
#pragma unroll
            for (int i = 0; i < 2; i++) {
                const int r = wm0 + i * 16 + g;
                aH[i][0] = *(const uint32_t*)&sAh[r * KS_STR + kk];
                aH[i][1] = *(const uint32_t*)&sAh[(r + 8) * KS_STR + kk];
                aH[i][2] = *(const uint32_t*)&sAh[r * KS_STR + kk + 8];
                aH[i][3] = *(const uint32_t*)&sAh[(r + 8) * KS_STR + kk + 8];
                aL[i][0] = *(const uint32_t*)&sAl[r * KS_STR + kk];
                aL[i][1] = *(const uint32_t*)&sAl[(r + 8) * KS_STR + kk];
                aL[i][2] = *(const uint32_t*)&sAl[r * KS_STR + kk + 8];
                aL[i][3] = *(const uint32_t*)&sAl[(r + 8) * KS_STR + kk + 8];
            }
#pragma unroll
            for (int j = 0; j < 8; j++) {
                const int n = wn0 + j * 8 + g;
                bH[j][0] = *(const uint32_t*)&sBh[n * KS_STR + kk];
                bH[j][1] = *(const uint32_t*)&sBh[n * KS_STR + kk + 8];
                bL[j][0] = *(const uint32_t*)&sBl[n * KS_STR + kk];
                bL[j][1] = *(const uint32_t*)&sBl[n * KS_STR + kk + 8];
            }
#pragma unroll
            for (int i = 0; i < 2; i++)
#pragma unroll
                for (int j = 0; j < 8; j++) {
                    mma_bf16(acc[i][j], aH[i], bH[j]);
                    mma_bf16(acc[i][j], aH[i], bL[j]);
                    mma_bf16(acc[i][j], aL[i], bH[j]);
                }
        }
        __syncthreads();
    }
#pragma unroll
    for (int i = 0; i < 2; i++)
#pragma unroll
        for (int j = 0; j < 8; j++) {
            const int cc = n0 + wn0 + j * 8 + t4 * 2;
            const int hh = cc >> 6, dh = cc & 63;
            const float b0 = __ldg(&bias[cc]), b1 = __ldg(&bias[cc + 1]);
#pragma unroll
            for (int rr = 0; rr < 2; rr++) {
                const int r = m0 + wm0 + i * 16 + g + rr * 8;
                const int bidx = r / L, l = r - bidx * L;
                const float f0 = acc[i][j][rr * 2 + 0] + b0;
                const float f1 = acc[i][j][rr * 2 + 1] + b1;
                __nv_bfloat16 h0 = __float2bfloat16(f0);
                __nv_bfloat16 h1 = __float2bfloat16(f1);
                __nv_bfloat16 e0 = __float2bfloat16(f0 - __bfloat162float(h0));
                __nv_bfloat16 e1 = __float2bfloat16(f1 - __bfloat162float(h1));
                if (mode == 0) {
                    const size_t base = ((size_t)(bidx * NH + hh) * L + l) * DHD + dh;
                    *(__nv_bfloat162*)&outH[base] = __nv_bfloat162(h0, h1);
                    *(__nv_bfloat162*)&outL[base] = __nv_bfloat162(e0, e1);
                } else {
                    const size_t base = ((size_t)(bidx * NH + hh) * DHD + dh) * LK + l;
                    outH[base] = h0; outH[base + LK] = h1;
                    outL[base] = e0; outL[base + LK] = e1;
                }
            }
        }
}

// =================================================================================
// Tensor-core attention: cp.async double-buffered tiles, bf16 S23, banded GEMM1
// =================================================================================
#define OFF_KH  0
#define OFF_KL  9216
#define OFF_VTH 18432
#define OFF_VTL 27648
#define OFF_ES  36864
#define OFF_MS  55296
#define BUF_BYTES 55552

#define SM_S23 0
#define SM_SL  34816
#define SM_QH  52224
#define SM_QL  61440
#define SM_BUF 70656
#define SM_PH  181760
#define SM_PL  190976
#define SM_MR  200192
#define SM_LS  200448
#define SM_CS  200704
#define ATTN_SMEM 200960

__global__ __launch_bounds__(256, 1)
void attn_tc(const float* __restrict__ mask, float* __restrict__ out)
{
    extern __shared__ char smc[];
    const uint32_t sbu = smem_u32(smc);
    __nv_bfloat16* S23 = (__nv_bfloat16*)(smc + SM_S23);   // [128][SSTR]
    float* Sl = (float*)(smc + SM_SL);                      // [64][68]
    __nv_bfloat16* Qh = (__nv_bfloat16*)(smc + SM_QH);
    __nv_bfloat16* Ql = (__nv_bfloat16*)(smc + SM_QL);
    __nv_bfloat16* Ph = (__nv_bfloat16*)(smc + SM_PH);
    __nv_bfloat16* Pl = (__nv_bfloat16*)(smc + SM_PL);
    float* Mr = (float*)(smc + SM_MR);
    float* Ls = (float*)(smc + SM_LS);
    float* Cs = (float*)(smc + SM_CS);

    const int t = threadIdx.x, lane = t & 31, w = t >> 5;
    const int g = lane >> 2, t4 = lane & 3;
    const int sm0 = (w & 1) * 32, sn0 = (w >> 1) * 16;
    const int en0 = (w >> 2) * 64, emg = (w & 3) * 32;
    const int l0 = blockIdx.x * 64, hd = blockIdx.y, b = blockIdx.z;

    const __nv_bfloat16* Qhg = g_Qh + ((size_t)(b * NH + hd) * LQ + l0) * DHD;
    const __nv_bfloat16* Qlg = g_Ql + ((size_t)(b * NH + hd) * LQ + l0) * DHD;
    const __nv_bfloat16* Khg = g_Kh + (size_t)(b * NH + hd) * LK * DHD;
    const __nv_bfloat16* Klg = g_Kl + (size_t)(b * NH + hd) * LK * DHD;
    const __nv_bfloat16* Vhg = g_VtH + (size_t)(b * NH + hd) * DHD * LK;
    const __nv_bfloat16* Vlg = g_VtL + (size_t)(b * NH + hd) * DHD * LK;
    const float* mg = mask + (size_t)b * LK;

    // Q tiles + first K/V/E/mask tiles: one cp.async group
#pragma unroll
    for (int i = 0; i < 2; i++) {
        int q = t + 256 * i, row = q >> 3, c = q & 7;
        cp_async16(sbu + SM_QH + row * 144 + c * 16, Qhg + row * DHD + c * 8);
        cp_async16(sbu + SM_QL + row * 144 + c * 16, Qlg + row * DHD + c * 8);
        cp_async16(sbu + SM_BUF + OFF_KH + row * 144 + c * 16, Khg + (size_t)row * DHD + c * 8);
        cp_async16(sbu + SM_BUF + OFF_KL + row * 144 + c * 16, Klg + (size_t)row * DHD + c * 8);
        cp_async16(sbu + SM_BUF + OFF_VTH + row * 144 + c * 16, Vhg + (size_t)row * LK + c * 8);
        cp_async16(sbu + SM_BUF + OFF_VTL + row * 144 + c * 16, Vlg + (size_t)row * LK + c * 8);
    }
    {
        const int eb0 = l0 + (MAXPOS - 64);
#pragma unroll
        for (int i = 0; i < 4; i++) {
            int q = t + 256 * i;
            if (q < 127 * 8) {
                int row = q >> 3, c = q & 7;
                cp_async16(sbu + SM_BUF + OFF_ES + row * 144 + c * 16,
                           g_EbH + (size_t)(eb0 + row) * DHD + c * 8);
            }
        }
        if (t < 16) cp_async16(sbu + SM_BUF + OFF_MS + t * 16, mg + t * 4);
    }
    cp_commit();

    if (t < 64) { Mr[t] = -1e30f; Ls[t] = 0.f; }
    if (t < 72) {  // zero Es row 127 in both buffers
        int bb = t / 36, wd = t % 36;
        *(uint32_t*)(smc + SM_BUF + bb * BUF_BYTES + OFF_ES + 127 * 144 + wd * 4) = 0u;
    }

    float O[2][2][4];
#pragma unroll
    for (int i = 0; i < 2; i++)
#pragma unroll
        for (int j = 0; j < 2; j++)
#pragma unroll
            for (int q = 0; q < 4; q++) O[i][j][q] = 0.f;

    const int wlo = (emg == 32 || emg == 64) ? 32 : 0;  // GEMM1 diagonal band

    for (int kt = 0; kt < LK / 64; kt++) {
        const int bb = kt & 1;
        const char* B = smc + SM_BUF + bb * BUF_BYTES;
        cp_wait<0>();
        __syncthreads();

        if (kt + 1 < LK / 64) {  // prefetch next tiles
            const int r1 = (kt + 1) * 64;
            const uint32_t P = sbu + SM_BUF + (bb ^ 1) * BUF_BYTES;
#pragma unroll
            for (int i = 0; i < 2; i++) {
                int q = t + 256 * i, row = q >> 3, c = q & 7;
                cp_async16(P + OFF_KH + row * 144 + c * 16, Khg + (size_t)(r1 + row) * DHD + c * 8);
                cp_async16(P + OFF_KL + row * 144 + c * 16, Klg + (size_t)(r1 + row) * DHD + c * 8);
                cp_async16(P + OFF_VTH + row * 144 + c * 16, Vhg + (size_t)row * LK + r1 + c * 8);
                cp_async16(P + OFF_VTL + row * 144 + c * 16, Vlg + (size_t)row * LK + r1 + c * 8);
            }
            const int eb1 = l0 - r1 + (MAXPOS - 64);
#pragma unroll
            for (int i = 0; i < 4; i++) {
                int q = t + 256 * i;
                if (q < 127 * 8) {
                    int row = q >> 3, c = q & 7;
                    cp_async16(P + OFF_ES + row * 144 + c * 16,
                               g_EbH + (size_t)(eb1 + row) * DHD + c * 8);
                }
            }
            if (t < 16) cp_async16(P + OFF_MS + t * 16, mg + r1 + t * 4);
            cp_commit();
        }

        const __nv_bfloat16* KhS = (const __nv_bfloat16*)(B + OFF_KH);
        const __nv_bfloat16* KlS = (const __nv_bfloat16*)(B + OFF_KL);
        const __nv_bfloat16* VhS = (const __nv_bfloat16*)(B + OFF_VTH);
        const __nv_bfloat16* VlS = (const __nv_bfloat16*)(B + OFF_VTL);
        const __nv_bfloat16* EsS = (const __nv_bfloat16*)(B + OFF_ES);
        const float* MsS = (const float*)(B + OFF_MS);

        // ---- GEMM1 (banded): S23 = [Qh;Kh] @ Es^T ----
        {
            const __nv_bfloat16* Ab = ((w & 3) < 2) ? Qh : KhS;
            const int am = (w & 1) * 32;
            float ea[2][8][4];
#pragma unroll
            for (int i = 0; i < 2; i++)
#pragma unroll
                for (int j = 0; j < 8; j++)
#pragma unroll
                    for (int q = 0; q < 4; q++) ea[i][j][q] = 0.f;
#pragma unroll
            for (int k4 = 0; k4 < 4; k4++) {
                const int kk = k4 * 16 + t4 * 2;
                uint32_t af[2][4];
#pragma unroll
                for (int i = 0; i < 2; i++) {
                    const int r = am + i * 16 + g;
                    af[i][0] = *(const uint32_t*)&Ab[r * STR + kk];
                    af[i][1] = *(const uint32_t*)&Ab[(r + 8) * STR + kk];
                    af[i][2] = *(const uint32_t*)&Ab[r * STR + kk + 8];
                    af[i][3] = *(const uint32_t*)&Ab[(r + 8) * STR + kk + 8];
                }
#pragma unroll
                for (int j = 0; j < 8; j++) {
                    const int nb = en0 + j * 8;
                    if (nb >= wlo && nb < wlo + 96) {
                        const int n = nb + g;
                        uint32_t bf2[2];
                        bf2[0] = *(const uint32_t*)&EsS[n * STR + kk];
                        bf2[1] = *(const uint32_t*)&EsS[n * STR + kk + 8];
                        mma_bf16(ea[0][j], af[0], bf2);
                        mma_bf16(ea[1][j], af[1], bf2);
                    }
                }
            }
#pragma unroll
            for (int i = 0; i < 2; i++)
#pragma unroll
                for (int j = 0; j < 8; j++) {
                    const int nb = en0 + j * 8;
                    if (nb >= wlo && nb < wlo + 96) {
                        const int m = emg + i * 16 + g, n = nb + t4 * 2;
                        *(uint32_t*)&S23[m * SSTR + n] = bfpack(ea[i][j][0], ea[i][j][1]);
                        *(uint32_t*)&S23[(m + 8) * SSTR + n] = bfpack(ea[i][j][2], ea[i][j][3]);
                    }
                }
        }
        // ---- GEMM2: Q@K^T (split) ----
        float sc[2][2][4];
#pragma unroll
        for (int i = 0; i < 2; i++)
#pragma unroll
            for (int j = 0; j < 2; j++)
#pragma unroll
                for (int q = 0; q < 4; q++) sc[i][j][q] = 0.f;
#pragma unroll
        for (int k4 = 0; k4 < 4; k4++) {
            const int kk = k4 * 16 + t4 * 2;
            uint32_t aH[2][4], aL[2][4];
#pragma unroll
            for (int i = 0; i < 2; i++) {
                const int r = sm0 + i * 16 + g;
                aH[i][0] = *(const uint32_t*)&Qh[r * STR + kk];
                aH[i][1] = *(const uint32_t*)&Qh[(r + 8) * STR + kk];
                aH[i][2] = *(const uint32_t*)&Qh[r * STR + kk + 8];
                aH[i][3] = *(const uint32_t*)&Qh[(r + 8) * STR + kk + 8];
                aL[i][0] = *(const uint32_t*)&Ql[r * STR + kk];
                aL[i][1] = *(const uint32_t*)&Ql[(r + 8) * STR + kk];
                aL[i][2] = *(const uint32_t*)&Ql[r * STR + kk + 8];
                aL[i][3] = *(const uint32_t*)&Ql[(r + 8) * STR + kk + 8];
            }
#pragma unroll
            for (int j = 0; j < 2; j++) {
                const int n = sn0 + j * 8 + g;
                uint32_t bH2[2], bL2[2];
                bH2[0] = *(const uint32_t*)&KhS[n * STR + kk];
                bH2[1] = *(const uint32_t*)&KhS[n * STR + kk + 8];
                bL2[0] = *(const uint32_t*)&KlS[n * STR + kk];
                bL2[1] = *(const uint32_t*)&KlS[n * STR + kk + 8];
#pragma unroll
                for (int i = 0; i < 2; i++) {
                    mma_bf16(sc[i][j], aH[i], bH2);
                    mma_bf16(sc[i][j], aH[i], bL2);
                    mma_bf16(sc[i][j], aL[i], bH2);
                }
            }
        }
        __syncthreads();

        // ---- logits: gather S23 diagonals + mask ----
#pragma unroll
        for (int i = 0; i < 2; i++)
#pragma unroll
            for (int j = 0; j < 2; j++) {
                const int ri = sn0 + j * 8 + t4 * 2;
#pragma unroll
                for (int ch = 0; ch < 2; ch++) {
                    const int li = sm0 + i * 16 + g + ch * 8;
                    const int nn = li - ri + 63;
                    float t0 = __bfloat162float(S23[li * SSTR + nn])
                             + __bfloat162float(S23[(64 + ri) * SSTR + nn]);
                    float t1 = __bfloat162float(S23[li * SSTR + nn - 1])
                             + __bfloat162float(S23[(65 + ri) * SSTR + nn - 1]);
                    float2 lv;
                    lv.x = (sc[i][j][ch * 2 + 0] + t0) * 0.125f + MsS[ri];
                    lv.y = (sc[i][j][ch * 2 + 1] + t1) * 0.125f + MsS[ri + 1];
                    *(float2*)&Sl[li * 68 + ri] = lv;
                }
            }
        __syncthreads();

        // ---- online softmax (4 threads/row) ----
        {
            const int row = t >> 2, qq = t & 3;
            float v[16], mx = -1e30f;
#pragma unroll
            for (int c = 0; c < 16; c++) {
                v[c] = Sl[row * 68 + qq * 16 + c];
                mx = fmaxf(mx, v[c]);
            }
            mx = fmaxf(mx, __shfl_xor_sync(0xffffffffu, mx, 1));
            mx = fmaxf(mx, __shfl_xor_sync(0xffffffffu, mx, 2));
            const float mold = Mr[row];
            const float mnew = fmaxf(mold, mx);
            const float corr = __expf(mold - mnew);
            float s = 0.f;
#pragma unroll
            for (int c = 0; c < 16; c++) { v[c] = __expf(v[c] - mnew); s += v[c]; }
            s += __shfl_xor_sync(0xffffffffu, s, 1);
            s += __shfl_xor_sync(0xffffffffu, s, 2);
            if (qq == 0) { Ls[row] = Ls[row] * corr + s; Mr[row] = mnew; Cs[row] = corr; }
#pragma unroll
            for (int c = 0; c < 16; c += 2) {
                uint32_t hi, lo; bfsplit(v[c], v[c + 1], hi, lo);
                *(uint32_t*)&Ph[row * STR + qq * 16 + c] = hi;
                *(uint32_t*)&Pl[row * STR + qq * 16 + c] = lo;
            }
        }
        __syncthreads();

        // ---- PV ----
#pragma unroll
        for (int i = 0; i < 2; i++) {
            const float c0 = Cs[sm0 + i * 16 + g];
            const float c1 = Cs[sm0 + i * 16 + g + 8];
#pragma unroll
            for (int j = 0; j < 2; j++) {
                O[i][j][0] *= c0; O[i][j][1] *= c0;
                O[i][j][2] *= c1; O[i][j][3] *= c1;
            }
        }
#pragma unroll
        for (int k4 = 0; k4 < 4; k4++) {
            const int kk = k4 * 16 + t4 * 2;
            uint32_t aH[2][4], aL[2][4];
#pragma unroll
            for (int i = 0; i < 2; i++) {
                const int r = sm0 + i * 16 + g;
                aH[i][0] = *(const uint32_t*)&Ph[r * STR + kk];
                aH[i][1] = *(const uint32_t*)&Ph[(r + 8) * STR + kk];
                aH[i][2] = *(const uint32_t*)&Ph[r * STR + kk + 8];
                aH[i][3] = *(const uint32_t*)&Ph[(r + 8) * STR + kk + 8];
                aL[i][0] = *(const uint32_t*)&Pl[r * STR + kk];
                aL[i][1] = *(const uint32_t*)&Pl[(r + 8) * STR + kk];
                aL[i][2] = *(const uint32_t*)&Pl[r * STR + kk + 8];
                aL[i][3] = *(const uint32_t*)&Pl[(r + 8) * STR + kk + 8];
            }
#pragma unroll
            for (int j = 0; j < 2; j++) {
                const int d = sn0 + j * 8 + g;
                uint32_t bH2[2], bL2[2];
                bH2[0] = *(const uint32_t*)&VhS[d * STR + kk];
                bH2[1] = *(const uint32_t*)&VhS[d * STR + kk + 8];
                bL2[0] = *(const uint32_t*)&VlS[d * STR + kk];
                bL2[1] = *(const uint32_t*)&VlS[d * STR + kk + 8];
#pragma unroll
                for (int i = 0; i < 2; i++) {
                    mma_bf16(O[i][j], aH[i], bH2);
                    mma_bf16(O[i][j], aH[i], bL2);
                    mma_bf16(O[i][j], aL[i], bH2);
                }
            }
        }
    }

    // ---- output [B, Lq, H*64] ----
#pragma unroll
    for (int i = 0; i < 2; i++)
#pragma unroll
        for (int ch = 0; ch < 2; ch++) {
            const int li = sm0 + i * 16 + g + ch * 8;
            const float inv = 1.0f / Ls[li];
#pragma unroll
            for (int j = 0; j < 2; j++) {
                const int d = sn0 + j * 8 + t4 * 2;
                float2 o;
                o.x = O[i][j][ch * 2 + 0] * inv;
                o.y = O[i][j][ch * 2 + 1] * inv;
                *(float2*)(out + ((size_t)(b * LQ) + l0 + li) * DM + hd * 64 + d) = o;
            }
        }
}

// =================================================================================
extern "C" void kernel_launch(void* const* d_in, const int* in_sizes, int n_in,
                              void* d_out, int out_size)
{
    const float* hidden   = (const float*)d_in[0];
    const float* q_hidden = (const float*)d_in[1];
    const float* mask     = (const float*)d_in[2];
    const float* Wq       = (const float*)d_in[3];
    const float* bq       = (const float*)d_in[4];
    const float* Wk       = (const float*)d_in[5];
    const float* bk       = (const float*)d_in[6];
    const float* Wv       = (const float*)d_in[7];
    const float* bv       = (const float*)d_in[8];
    const float* dist     = (const float*)d_in[9];
    float* out = (float*)d_out;

    __nv_bfloat16 *Qh, *Ql, *Kh, *Kl, *VtH, *VtL, *EbH;
    __nv_bfloat16 *Xqh, *Xql, *Xkh, *Xkl, *Wh, *Wl;
    cudaGetSymbolAddress((void**)&Qh,  g_Qh);
    cudaGetSymbolAddress((void**)&Ql,  g_Ql);
    cudaGetSymbolAddress((void**)&Kh,  g_Kh);
    cudaGetSymbolAddress((void**)&Kl,  g_Kl);
    cudaGetSymbolAddress((void**)&VtH, g_VtH);
    cudaGetSymbolAddress((void**)&VtL, g_VtL);
    cudaGetSymbolAddress((void**)&EbH, g_EbH);
    cudaGetSymbolAddress((void**)&Xqh, g_Xqh);
    cudaGetSymbolAddress((void**)&Xql, g_Xql);
    cudaGetSymbolAddress((void**)&Xkh, g_Xkh);
    cudaGetSymbolAddress((void**)&Xkl, g_Xkl);
    cudaGetSymbolAddress((void**)&Wh,  g_Wh);
    cudaGetSymbolAddress((void**)&Wl,  g_Wl);

    cudaFuncSetAttribute(proj_tc, cudaFuncAttributeMaxDynamicSharedMemorySize,
                         PROJ_SMEM_BYTES);
    cudaFuncSetAttribute(attn_tc, cudaFuncAttributeMaxDynamicSharedMemorySize,
                         ATTN_SMEM);

    const int nq = NB * LQ * DM / 4;
    const int nk = NB * LK * DM / 4;
    const int nw = DM * DM / 4;
    const int ne = (2 * MAXPOS - 1) * DHD / 4;
    split_kernel<<<(nq + 255) / 256, 256>>>(q_hidden, Xqh, Xql, nq);
    split_kernel<<<(nk + 255) / 256, 256>>>(hidden,   Xkh, Xkl, nk);
    split_kernel<<<(nw + 255) / 256, 256>>>(Wq, Wh + 0 * (size_t)DM * DM, Wl + 0 * (size_t)DM * DM, nw);
    split_kernel<<<(nw + 255) / 256, 256>>>(Wk, Wh + 1 * (size_t)DM * DM, Wl + 1 * (size_t)DM * DM, nw);
    split_kernel<<<(nw + 255) / 256, 256>>>(Wv, Wh + 2 * (size_t)DM * DM, Wl + 2 * (size_t)DM * DM, nw);
    conv_kernel<<<(ne + 255) / 256, 256>>>(dist, EbH, ne);

    dim3 gq(NB * LQ / 128, DM / 128);
    dim3 gk(NB * LK / 128, DM / 128);
    proj_tc<<<gq, 256, PROJ_SMEM_BYTES>>>(Xqh, Xql,
        Wh + 0 * (size_t)DM * DM, Wl + 0 * (size_t)DM * DM, bq, Qh, Ql, LQ, 0);
    proj_tc<<<gk, 256, PROJ_SMEM_BYTES>>>(Xkh, Xkl,
        Wh + 1 * (size_t)DM * DM, Wl + 1 * (size_t)DM * DM, bk, Kh, Kl, LK, 0);
    proj_tc<<<gk, 256, PROJ_SMEM_BYTES>>>(Xkh, Xkl,
        Wh + 2 * (size_t)DM * DM, Wl + 2 * (size_t)DM * DM, bv, VtH, VtL, LK, 1);

    dim3 ga(LQ / 64, NH, NB);
    attn_tc<<<ga, 256, ATTN_SMEM>>>(mask, out);
}